// round 8
// baseline (speedup 1.0000x reference)
#include <cuda_runtime.h>
#include <cstdint>

#define D 4096
#define THREADS 256
#define OCC 6

__device__ __forceinline__ uint32_t smem_u32(const void* p) {
    uint32_t a;
    asm("{ .reg .u64 t; cvta.to.shared.u64 t, %1; cvt.u32.u64 %0, t; }"
        : "=r"(a) : "l"(p));
    return a;
}

// async 16B copy gmem -> smem (bypasses L1/registers)
__device__ __forceinline__ void cp16(uint32_t dst, const float* src) {
    asm volatile("cp.async.cg.shared.global [%0], [%1], 16;"
                 :: "r"(dst), "l"(src) : "memory");
}
__device__ __forceinline__ void cp_commit() {
    asm volatile("cp.async.commit_group;" ::: "memory");
}
__device__ __forceinline__ void cp_wait1() {
    asm volatile("cp.async.wait_group 1;" ::: "memory");
}

// Packed butterfly via f32x2: 2 butterflies in 2 instructions.
__device__ __forceinline__ void bfly2(float& a0, float& a1, float& b0, float& b1) {
    asm("{\n\t"
        ".reg .b32 m;\n\t"
        ".reg .b64 ra, rb, rs, rd, rn;\n\t"
        "mov.b32 m, 0xBF800000;\n\t"
        "mov.b64 rn, {m, m};\n\t"
        "mov.b64 ra, {%0, %1};\n\t"
        "mov.b64 rb, {%2, %3};\n\t"
        "add.rn.f32x2 rs, ra, rb;\n\t"
        "fma.rn.f32x2 rd, rb, rn, ra;\n\t"
        "mov.b64 {%0, %1}, rs;\n\t"
        "mov.b64 {%2, %3}, rd;\n\t"
        "}" : "+f"(a0), "+f"(a1), "+f"(b0), "+f"(b1));
}

__device__ __forceinline__ void scale2(float& a0, float& a1, float c) {
    asm("{\n\t"
        ".reg .b64 ra, rs, rm;\n\t"
        "mov.b64 ra, {%0, %1};\n\t"
        "mov.b64 rs, {%2, %2};\n\t"
        "mul.rn.f32x2 rm, ra, rs;\n\t"
        "mov.b64 {%0, %1}, rm;\n\t"
        "}" : "+f"(a0), "+f"(a1) : "f"(c));
}

// 16-point FWHT: reg bits 1..3 packed (pairs along bit 0), bit 0 scalar.
__device__ __forceinline__ void fwht16p(float r[16]) {
#pragma unroll
    for (int hp = 1; hp < 8; hp <<= 1) {
#pragma unroll
        for (int m = 0; m < 8; m++) {
            if (!(m & hp)) {
                bfly2(r[2 * m], r[2 * m + 1],
                      r[2 * (m | hp)], r[2 * (m | hp) + 1]);
            }
        }
    }
#pragma unroll
    for (int m = 0; m < 8; m++) {
        float a = r[2 * m], b = r[2 * m + 1];
        r[2 * m]     = a + b;
        r[2 * m + 1] = a - b;
    }
}

__global__ __launch_bounds__(THREADS, OCC)
void rht_kernel(const float* __restrict__ x,
                const float* __restrict__ signs,
                float* __restrict__ out,
                int n_rows, int stride) {
    // two 16KB row buffers: staging AND in-place workspace (ring of 2)
    __shared__ __align__(16) float stage[2][D];

    const int t = threadIdx.x;
    // sigma(t): intra-warp involution. Thread t reads raw float4 slot u,
    // writes transformed data to plain slot t -> shared image == swizzled
    // layout phys = i ^ ((i>>4)&0x1C) used by passes B/C (verified R6).
    const int u = t ^ ((t >> 4) & 7);

    const int base2 = ((t >> 2) << 6) | (t & 3);
    const int sb2   = base2 ^ ((base2 >> 4) & 0x1C);
    const int base3 = ((t >> 6) << 10) | (t & 63);   // bits 6..9 zero

    const uint32_t st32_0 = smem_u32(&stage[0][0]);
    const uint32_t st32_1 = smem_u32(&stage[1][0]);

    // sign bitmask for logical indices (h<<10)|(u<<2)|j  (signs are exactly +/-1)
    unsigned smask = 0;
#pragma unroll
    for (int h = 0; h < 4; h++) {
#pragma unroll
        for (int j = 0; j < 4; j++) {
            smask |= (__float_as_uint(signs[(h << 10) | (u << 2) | j]) >> 31)
                     << (h * 4 + j);
        }
    }

    int row = blockIdx.x;

    // prologue: group0 = row -> stage0, group1 = row+stride -> stage1
    {
        const float* src = x + (size_t)row * D;
#pragma unroll
        for (int h = 0; h < 4; h++) {
            cp16(st32_0 + (((h << 8) + t) << 4), src + (h << 10) + (t << 2));
        }
        cp_commit();
        const int r1 = row + stride;
        if (r1 < n_rows) {
            const float* s1 = x + (size_t)r1 * D;
#pragma unroll
            for (int h = 0; h < 4; h++) {
                cp16(st32_1 + (((h << 8) + t) << 4), s1 + (h << 10) + (t << 2));
            }
        }
        cp_commit();   // always commit (possibly-empty group keeps counting sane)
    }

    int q = 0;
    while (row < n_rows) {
        cp_wait1();        // oldest group (current buffer) complete
        __syncthreads();   // visible to all threads

        float r[16];
        float* __restrict__ sb = stage[q];

        // ---- Pass A: LDS.128 raw at float4 slot (h<<8)+u; sign; fwht ----
        {
            const float4* sp = reinterpret_cast<const float4*>(sb);
#pragma unroll
            for (int h = 0; h < 4; h++) {
                float4 v = sp[(h << 8) + u];
                const float w[4] = { v.x, v.y, v.z, v.w };
#pragma unroll
                for (int j = 0; j < 4; j++) {
                    const int b = h * 4 + j;
                    r[b] = __uint_as_float(__float_as_uint(w[j]) ^
                                           ((smask << (31 - b)) & 0x80000000u));
                }
            }
        }
        fwht16p(r);
        __syncwarp();      // read<->write exchange is intra-warp only
        {
            float4* wp = reinterpret_cast<float4*>(sb);
#pragma unroll
            for (int h = 0; h < 4; h++) {
                wp[(h << 8) + t] = make_float4(r[h * 4 + 0], r[h * 4 + 1],
                                               r[h * 4 + 2], r[h * 4 + 3]);
            }
        }
        __syncthreads();

        // ---- Pass B: bits {2,3,4,5} (identical to R6) ----
#pragma unroll
        for (int k = 0; k < 16; k++) r[k] = sb[sb2 ^ (k << 2)];
        fwht16p(r);
#pragma unroll
        for (int k = 0; k < 16; k++) sb[sb2 ^ (k << 2)] = r[k];
        __syncthreads();

        // ---- Pass C: bits {6,7,8,9} (identical to R6) ----
#pragma unroll
        for (int k = 0; k < 16; k++) {
            r[k] = sb[base3 ^ (k << 6) ^ ((k & 7) << 2)];
        }
        fwht16p(r);
#pragma unroll
        for (int m = 0; m < 8; m++) scale2(r[2 * m], r[2 * m + 1], 0.015625f);

        float* __restrict__ orow = out + (size_t)row * D;
#pragma unroll
        for (int k = 0; k < 16; k++) orow[base3 + (k << 6)] = r[k];

        __syncthreads();   // all pass-C reads done before refill overwrites

        // ---- refill this buffer with row + 2*stride ----
        const int row2 = row + 2 * stride;
        if (row2 < n_rows) {
            const float* src = x + (size_t)row2 * D;
            const uint32_t dst = q ? st32_1 : st32_0;
#pragma unroll
            for (int h = 0; h < 4; h++) {
                cp16(dst + (((h << 8) + t) << 4), src + (h << 10) + (t << 2));
            }
        }
        cp_commit();

        row += stride;
        q ^= 1;
    }
}

extern "C" void kernel_launch(void* const* d_in, const int* in_sizes, int n_in,
                              void* d_out, int out_size) {
    const float* x     = (const float*)d_in[0];
    const float* signs = (const float*)d_in[1];
    float* out = (float*)d_out;

    const int n_rows = in_sizes[0] / D;  // 8192

    int sm_count = 152;
    cudaDeviceGetAttribute(&sm_count, cudaDevAttrMultiProcessorCount, 0);
    int grid = sm_count * OCC;           // one persistent wave
    if (grid > n_rows) grid = n_rows;

    rht_kernel<<<grid, THREADS>>>(x, signs, out, n_rows, grid);
}

// round 9
// speedup vs baseline: 1.0752x; 1.0752x over previous
#include <cuda_runtime.h>
#include <cstdint>

#define D 4096
#define THREADS 256
#define OCC 6
#define ROW_BYTES (D * 4)

// ---------------- mbarrier + TMA bulk helpers ----------------
__device__ __forceinline__ uint32_t smem_u32(const void* p) {
    uint32_t a;
    asm("{ .reg .u64 t; cvta.to.shared.u64 t, %1; cvt.u32.u64 %0, t; }"
        : "=r"(a) : "l"(p));
    return a;
}
__device__ __forceinline__ void mbar_init(uint32_t mbar, uint32_t cnt) {
    asm volatile("mbarrier.init.shared.b64 [%0], %1;" :: "r"(mbar), "r"(cnt) : "memory");
}
__device__ __forceinline__ void mbar_expect_tx(uint32_t mbar, uint32_t bytes) {
    asm volatile("mbarrier.arrive.expect_tx.shared.b64 _, [%0], %1;"
                 :: "r"(mbar), "r"(bytes) : "memory");
}
__device__ __forceinline__ void bulk_g2s(uint32_t dst, const void* src,
                                         uint32_t bytes, uint32_t mbar) {
    asm volatile("cp.async.bulk.shared::cta.global.mbarrier::complete_tx::bytes "
                 "[%0], [%1], %2, [%3];"
                 :: "r"(dst), "l"(src), "r"(bytes), "r"(mbar) : "memory");
}
__device__ __forceinline__ void mbar_wait(uint32_t mbar, uint32_t parity) {
    asm volatile(
        "{\n\t"
        ".reg .pred P;\n\t"
        "WAIT_%=:\n\t"
        "mbarrier.try_wait.parity.acquire.cta.shared::cta.b64 P, [%0], %1, 0x989680;\n\t"
        "@P bra.uni DONE_%=;\n\t"
        "bra.uni WAIT_%=;\n\t"
        "DONE_%=:\n\t"
        "}" :: "r"(mbar), "r"(parity) : "memory");
}

// ---------------- packed f32x2 math ----------------
__device__ __forceinline__ void bfly2(float& a0, float& a1, float& b0, float& b1) {
    asm("{\n\t"
        ".reg .b32 m;\n\t"
        ".reg .b64 ra, rb, rs, rd, rn;\n\t"
        "mov.b32 m, 0xBF800000;\n\t"
        "mov.b64 rn, {m, m};\n\t"
        "mov.b64 ra, {%0, %1};\n\t"
        "mov.b64 rb, {%2, %3};\n\t"
        "add.rn.f32x2 rs, ra, rb;\n\t"
        "fma.rn.f32x2 rd, rb, rn, ra;\n\t"
        "mov.b64 {%0, %1}, rs;\n\t"
        "mov.b64 {%2, %3}, rd;\n\t"
        "}" : "+f"(a0), "+f"(a1), "+f"(b0), "+f"(b1));
}
__device__ __forceinline__ void scale2(float& a0, float& a1, float c) {
    asm("{\n\t"
        ".reg .b64 ra, rs, rm;\n\t"
        "mov.b64 ra, {%0, %1};\n\t"
        "mov.b64 rs, {%2, %2};\n\t"
        "mul.rn.f32x2 rm, ra, rs;\n\t"
        "mov.b64 {%0, %1}, rm;\n\t"
        "}" : "+f"(a0), "+f"(a1) : "f"(c));
}

// 16-point FWHT: reg bits 1..3 packed, bit 0 scalar (verified R6-R8).
__device__ __forceinline__ void fwht16p(float r[16]) {
#pragma unroll
    for (int hp = 1; hp < 8; hp <<= 1) {
#pragma unroll
        for (int m = 0; m < 8; m++) {
            if (!(m & hp)) {
                bfly2(r[2 * m], r[2 * m + 1],
                      r[2 * (m | hp)], r[2 * (m | hp) + 1]);
            }
        }
    }
#pragma unroll
    for (int m = 0; m < 8; m++) {
        float a = r[2 * m], b = r[2 * m + 1];
        r[2 * m]     = a + b;
        r[2 * m + 1] = a - b;
    }
}

__global__ __launch_bounds__(THREADS, OCC)
void rht_kernel(const float* __restrict__ x,
                const float* __restrict__ signs,
                float* __restrict__ out,
                int n_rows, int stride) {
    __shared__ __align__(16) float stage[2][D];
    __shared__ __align__(8)  unsigned long long mbar[2];

    const int t = threadIdx.x;
    // sigma(t): intra-warp involution; read raw float4 slot u, write slot t
    // => shared image equals phys = i ^ ((i>>4)&0x1C) layout (verified R8).
    const int u = t ^ ((t >> 4) & 7);

    const int base2 = ((t >> 2) << 6) | (t & 3);
    const int sb2   = base2 ^ ((base2 >> 4) & 0x1C);
    const int base3 = ((t >> 6) << 10) | (t & 63);

    const uint32_t st32[2] = { smem_u32(&stage[0][0]), smem_u32(&stage[1][0]) };
    const uint32_t mb32[2] = { smem_u32(&mbar[0]),     smem_u32(&mbar[1])     };

    // sign bitmask at logical indices (h<<10)|(u<<2)|j (signs are exactly +/-1)
    unsigned smask = 0;
#pragma unroll
    for (int h = 0; h < 4; h++) {
#pragma unroll
        for (int j = 0; j < 4; j++) {
            smask |= (__float_as_uint(signs[(h << 10) | (u << 2) | j]) >> 31)
                     << (h * 4 + j);
        }
    }

    if (t == 0) {
        mbar_init(mb32[0], 1);
        mbar_init(mb32[1], 1);
    }
    __syncthreads();

    int row = blockIdx.x;

    // prologue: buffer0 <- row, buffer1 <- row+stride (TMA bulk, 1 thread)
    if (t == 0) {
        mbar_expect_tx(mb32[0], ROW_BYTES);
        bulk_g2s(st32[0], x + (size_t)row * D, ROW_BYTES, mb32[0]);
        const int r1 = row + stride;
        if (r1 < n_rows) {
            mbar_expect_tx(mb32[1], ROW_BYTES);
            bulk_g2s(st32[1], x + (size_t)r1 * D, ROW_BYTES, mb32[1]);
        }
    }

    int q = 0;
    unsigned ph[2] = { 0, 0 };

    while (row < n_rows) {
        // data for this row ready? (acquire orders TMA data for all threads)
        mbar_wait(mb32[q], ph[q]);
        ph[q] ^= 1;

        float r[16];
        float* __restrict__ sb = stage[q];

        // ---- Pass A: LDS.128 raw slot (h<<8)+u; sign-XOR; fwht; write slot t
        {
            const float4* sp = reinterpret_cast<const float4*>(sb);
#pragma unroll
            for (int h = 0; h < 4; h++) {
                float4 v = sp[(h << 8) + u];
                const float w[4] = { v.x, v.y, v.z, v.w };
#pragma unroll
                for (int j = 0; j < 4; j++) {
                    const int b = h * 4 + j;
                    r[b] = __uint_as_float(__float_as_uint(w[j]) ^
                                           ((smask << (31 - b)) & 0x80000000u));
                }
            }
        }
        fwht16p(r);
        __syncwarp();   // raw-read <-> transformed-write exchange is intra-warp
        {
            float4* wp = reinterpret_cast<float4*>(sb);
#pragma unroll
            for (int h = 0; h < 4; h++) {
                wp[(h << 8) + t] = make_float4(r[h * 4 + 0], r[h * 4 + 1],
                                               r[h * 4 + 2], r[h * 4 + 3]);
            }
        }
        __syncthreads();

        // ---- Pass B: bits {2,3,4,5} ----
#pragma unroll
        for (int k = 0; k < 16; k++) r[k] = sb[sb2 ^ (k << 2)];
        fwht16p(r);
#pragma unroll
        for (int k = 0; k < 16; k++) sb[sb2 ^ (k << 2)] = r[k];
        __syncthreads();

        // ---- Pass C: bits {6,7,8,9} ----
#pragma unroll
        for (int k = 0; k < 16; k++) {
            r[k] = sb[base3 ^ (k << 6) ^ ((k & 7) << 2)];
        }
        fwht16p(r);
#pragma unroll
        for (int m = 0; m < 8; m++) scale2(r[2 * m], r[2 * m + 1], 0.015625f);

        // coalesced stores at logical i = base3 + k*64
        float* __restrict__ orow = out + (size_t)row * D;
#pragma unroll
        for (int k = 0; k < 16; k++) orow[base3 + (k << 6)] = r[k];

        __syncthreads();   // all pass-C reads of buf q done before refill

        // ---- refill buf q with row + 2*stride (TMA bulk) ----
        const int row2 = row + 2 * stride;
        if (t == 0 && row2 < n_rows) {
            mbar_expect_tx(mb32[q], ROW_BYTES);
            bulk_g2s(st32[q], x + (size_t)row2 * D, ROW_BYTES, mb32[q]);
        }

        row += stride;
        q ^= 1;
    }
}

extern "C" void kernel_launch(void* const* d_in, const int* in_sizes, int n_in,
                              void* d_out, int out_size) {
    const float* x     = (const float*)d_in[0];
    const float* signs = (const float*)d_in[1];
    float* out = (float*)d_out;

    const int n_rows = in_sizes[0] / D;  // 8192

    int sm_count = 152;
    cudaDeviceGetAttribute(&sm_count, cudaDevAttrMultiProcessorCount, 0);
    int grid = sm_count * OCC;           // one persistent wave
    if (grid > n_rows) grid = n_rows;

    rht_kernel<<<grid, THREADS>>>(x, signs, out, n_rows, grid);
}